// round 15
// baseline (speedup 1.0000x reference)
#include <cuda_runtime.h>
#include <cuda_fp16.h>
#include <cstdint>
#include <math.h>

// ---------------------------------------------------------------------------
// GraphNeuralNetwork forward. GEMMs on mma.sync fp16 (m16n8k16, fp32 accum).
// R15: R14 + surgical gating -- ONLY se1/se2 (soh producers, ~95us) deferred
// behind gc2 so they fill the otherwise-idle spmm2 window without delaying
// the join (mlp1/mlp2 stay greedy). zero_s1 moved to stream B (parallel with
// conv_goh).
// ---------------------------------------------------------------------------

#define N_GO    40000
#define GO_FEAT 512
#define SEQ_FEAT 1280
#define NHID0   1024
#define NHID1   512
#define N_EDGES 640000
#define SEQ_B   4096

// ---------------- scratch (no runtime allocation allowed) ------------------
__device__ __half g_goh [(size_t)N_GO * GO_FEAT];
__device__ __half g_seqh[(size_t)SEQ_B * SEQ_FEAT];
__device__ __half g_t1h [(size_t)N_GO * NHID0];
__device__ __half g_xh  [(size_t)N_GO * NHID0];
__device__ __half g_g2h [(size_t)N_GO * NHID1];
__device__ __half g_uh  [(size_t)SEQ_B * NHID0];
__device__ __half g_soh [(size_t)SEQ_B * NHID0];
__device__ __half g_cath[(size_t)N_GO * 1024];
__device__ __half g_sp1h[(size_t)N_GO * NHID1];
__device__ float  g_s1  [(size_t)N_GO * NHID1];
__device__ float  g_s2  [(size_t)N_GO * NHID1];
__device__ __half g_wth[4456448];  // transposed half weights arena

static inline int cdiv(int a, int b) { return (a + b - 1) / b; }

// ---------------------------------------------------------------------------
__device__ __forceinline__ uint32_t smem_u32(const void* p) {
    uint32_t a;
    asm("{ .reg .u64 t; cvta.to.shared.u64 t, %1; cvt.u32.u64 %0, t; }"
        : "=r"(a) : "l"(p));
    return a;
}

__device__ __forceinline__ void mma_f16(float c[4], const uint32_t a[4],
                                        const uint32_t b[2]) {
    asm volatile(
        "mma.sync.aligned.m16n8k16.row.col.f32.f16.f16.f32 "
        "{%0,%1,%2,%3}, {%4,%5,%6,%7}, {%8,%9}, {%0,%1,%2,%3};"
        : "+f"(c[0]), "+f"(c[1]), "+f"(c[2]), "+f"(c[3])
        : "r"(a[0]), "r"(a[1]), "r"(a[2]), "r"(a[3]), "r"(b[0]), "r"(b[1]));
}

__device__ __forceinline__ void cp_async16(uint32_t dst, const void* src, bool valid) {
    int sz = valid ? 16 : 0;
    asm volatile("cp.async.cg.shared.global [%0], [%1], 16, %2;"
                 :: "r"(dst), "l"(src), "r"(sz) : "memory");
}
#define CP_COMMIT() asm volatile("cp.async.commit_group;" ::: "memory")
#define CP_WAIT2()  asm volatile("cp.async.wait_group 2;" ::: "memory")

// ---------------------------------------------------------------------------
// fp16 GEMM: C[M,N] = act(A[M,K] @ B[N,K]^T + bias). A rows lda halfs, B rows
// ldb halfs. CTA 128x128, K-tile 32, 4 warps (2x2, warp tile 64x64), 4-stage
// cp.async, pitch 40 halfs. act: 0=none 1=relu 2=sigmoid.
// C half if cHalf else float. Optional C2 (half, stride ldc2).
// swapxy: blockIdx.x indexes M.
// ---------------------------------------------------------------------------
#define PW 20
#define TILE_B 10240
#define STAGE_B (2 * TILE_B)
#define NSTAGE 4
#define GEMM_SMEM_BYTES (NSTAGE * STAGE_B)   // 81920
#define GEMM_T 128

__global__ void __launch_bounds__(GEMM_T, 2) gemm_h(
    const __half* __restrict__ A, int lda,
    const __half* __restrict__ B, int ldb,
    const float* __restrict__ bias,
    void* __restrict__ Cv, int cHalf,
    __half* __restrict__ C2, int ldc2,
    int M, int N, int K, int act, int swapxy)
{
    extern __shared__ __align__(16) char smc[];
    const uint32_t smem_base = smem_u32(smc);

    const int tid  = threadIdx.x;
    const int wid  = tid >> 5;
    const int lane = tid & 31;
    const int g    = lane >> 2;
    const int tig  = lane & 3;
    const int wm   = wid >> 1;
    const int wn   = wid & 1;
    const int m0   = (swapxy ? blockIdx.x : blockIdx.y) * 128;
    const int n0   = (swapxy ? blockIdx.y : blockIdx.x) * 128;

    const int nkt = K >> 5;

    auto issue = [&](int kt) {
        if (kt < nkt) {
            const int k0 = kt << 5;
            const uint32_t sbase = smem_base + (uint32_t)(kt % NSTAGE) * STAGE_B;
#pragma unroll
            for (int it = 0; it < 4; it++) {
                int idx = tid + it * GEMM_T;
                int r   = idx >> 2;
                int c   = idx & 3;
                uint32_t da = sbase + (uint32_t)(r * 80 + c * 16);
                cp_async16(da, A + (size_t)(m0 + r) * lda + k0 + c * 8, (m0 + r) < M);
                cp_async16(da + TILE_B, B + (size_t)(n0 + r) * ldb + k0 + c * 8,
                           (n0 + r) < N);
            }
        }
        CP_COMMIT();
    };

    float acc[4][8][4];
#pragma unroll
    for (int i = 0; i < 4; i++)
#pragma unroll
        for (int j = 0; j < 8; j++)
#pragma unroll
            for (int t = 0; t < 4; t++) acc[i][j][t] = 0.f;

    issue(0); issue(1); issue(2);

    const int arow = (wm * 64 + g) * PW;
    const int brow = (wn * 64 + g) * PW;

    for (int kt = 0; kt < nkt; kt++) {
        CP_WAIT2();
        __syncthreads();
        issue(kt + 3);

        const uint32_t* as = (const uint32_t*)(smc + (kt % NSTAGE) * STAGE_B);
        const uint32_t* bs = as + TILE_B / 4;
#pragma unroll
        for (int kk = 0; kk < 2; kk++) {
            const int ko = kk * 8 + tig;
            uint32_t af[4][4];
#pragma unroll
            for (int i = 0; i < 4; i++) {
                int base = arow + i * 16 * PW;
                af[i][0] = as[base + ko];
                af[i][1] = as[base + 8 * PW + ko];
                af[i][2] = as[base + ko + 4];
                af[i][3] = as[base + 8 * PW + ko + 4];
            }
            uint32_t bf[8][2];
#pragma unroll
            for (int j = 0; j < 8; j++) {
                int base = brow + j * 8 * PW;
                bf[j][0] = bs[base + ko];
                bf[j][1] = bs[base + ko + 4];
            }
#pragma unroll
            for (int i = 0; i < 4; i++)
#pragma unroll
                for (int j = 0; j < 8; j++)
                    mma_f16(acc[i][j], af[i], bf[j]);
        }
    }

    // ---- epilogue ----
#pragma unroll
    for (int i = 0; i < 4; i++) {
        const int r0 = m0 + wm * 64 + 16 * i + g;
#pragma unroll
        for (int j = 0; j < 8; j++) {
            const int cn = n0 + wn * 64 + 8 * j + 2 * tig;
            if (cn >= N) continue;
            float b0 = 0.f, b1 = 0.f;
            if (bias != nullptr) { b0 = bias[cn]; b1 = bias[cn + 1]; }
#pragma unroll
            for (int h = 0; h < 2; h++) {
                const int r = r0 + h * 8;
                if (r >= M) continue;
                float x0 = acc[i][j][2 * h]     + b0;
                float x1 = acc[i][j][2 * h + 1] + b1;
                if (act == 1) { x0 = fmaxf(x0, 0.f); x1 = fmaxf(x1, 0.f); }
                else if (act == 2) {
                    x0 = __fdividef(1.f, 1.f + __expf(-x0));
                    x1 = __fdividef(1.f, 1.f + __expf(-x1));
                }
                if (cHalf)
                    *(__half2*)((__half*)Cv + (size_t)r * N + cn) =
                        __floats2half2_rn(x0, x1);
                else
                    *(float2*)((float*)Cv + (size_t)r * N + cn) =
                        make_float2(x0, x1);
                if (C2)
                    *(__half2*)(C2 + (size_t)r * ldc2 + cn) =
                        __floats2half2_rn(x0, x1);
            }
        }
    }
}

// ---------------------------------------------------------------------------
__global__ void transpose_h(const float* __restrict__ in, __half* __restrict__ out,
                            int R, int C)
{
    __shared__ float t[32][33];
    int bx = blockIdx.x * 32, by = blockIdx.y * 32;
    int x = bx + threadIdx.x;
    int y = by + threadIdx.y;
#pragma unroll
    for (int j = 0; j < 32; j += 8)
        if (y + j < R && x < C) t[threadIdx.y + j][threadIdx.x] = in[(size_t)(y + j) * C + x];
    __syncthreads();
    x = by + threadIdx.x;
    y = bx + threadIdx.y;
#pragma unroll
    for (int j = 0; j < 32; j += 8)
        if (y + j < C && x < R)
            out[(size_t)(y + j) * R + x] = __float2half_rn(t[threadIdx.x][threadIdx.y + j]);
}

__global__ void conv_h(const float* __restrict__ in, __half* __restrict__ out, long n4)
{
    long i = blockIdx.x * (long)blockDim.x + threadIdx.x;
    long stride = (long)gridDim.x * blockDim.x;
    for (; i < n4; i += stride) {
        float4 v = ((const float4*)in)[i];
        ((__half2*)out)[2 * i]     = __floats2half2_rn(v.x, v.y);
        ((__half2*)out)[2 * i + 1] = __floats2half2_rn(v.z, v.w);
    }
}

// ---------------------------------------------------------------------------
// SpMM (COO): out[row] += val * x[col], x fp16, fp32 float4 atomics.
// Persistent warps; two edges per iteration.
// ---------------------------------------------------------------------------
__global__ void __launch_bounds__(256) spmm_h(
    const int* __restrict__ erow, const int* __restrict__ ecol,
    const float* __restrict__ eval, const __half* __restrict__ x,
    float* __restrict__ out, int nEdges, int d)
{
    const int lane = threadIdx.x & 31;
    const int gw   = (blockIdx.x * blockDim.x + threadIdx.x) >> 5;
    const int nw   = (gridDim.x * blockDim.x) >> 5;
    const int nch  = d >> 7;

    int e = gw * 2;
    const int step = nw * 2;
    for (; e + 1 < nEdges; e += step) {
        const int   r0 = erow[e],     r1 = erow[e + 1];
        const int   c0 = ecol[e],     c1 = ecol[e + 1];
        const float v0 = eval[e],     v1 = eval[e + 1];
        const __half2* xp0 = (const __half2*)(x + (size_t)c0 * d) + lane * 2;
        const __half2* xp1 = (const __half2*)(x + (size_t)c1 * d) + lane * 2;
        float4* op0 = (float4*)(out + (size_t)r0 * d) + lane;
        float4* op1 = (float4*)(out + (size_t)r1 * d) + lane;
        for (int ch = 0; ch < nch; ch++) {
            __half2 a0 = xp0[ch * 64], a1 = xp0[ch * 64 + 1];
            __half2 b0 = xp1[ch * 64], b1 = xp1[ch * 64 + 1];
            float2 fa0 = __half22float2(a0), fa1 = __half22float2(a1);
            float2 fb0 = __half22float2(b0), fb1 = __half22float2(b1);
            atomicAdd(op0 + ch * 32,
                      make_float4(v0 * fa0.x, v0 * fa0.y, v0 * fa1.x, v0 * fa1.y));
            atomicAdd(op1 + ch * 32,
                      make_float4(v1 * fb0.x, v1 * fb0.y, v1 * fb1.x, v1 * fb1.y));
        }
    }
    if (e < nEdges) {
        const int   r = erow[e];
        const int   c = ecol[e];
        const float v = eval[e];
        const __half2* xp = (const __half2*)(x + (size_t)c * d) + lane * 2;
        float4*        op = (float4*)(out + (size_t)r * d) + lane;
        for (int ch = 0; ch < nch; ch++) {
            float2 f0 = __half22float2(xp[ch * 64]);
            float2 f1 = __half22float2(xp[ch * 64 + 1]);
            atomicAdd(op + ch * 32,
                      make_float4(v * f0.x, v * f0.y, v * f1.x, v * f1.y));
        }
    }
}

__global__ void zero_kernel(float4* __restrict__ p, long n4)
{
    long i = blockIdx.x * (long)blockDim.x + threadIdx.x;
    long stride = (long)gridDim.x * blockDim.x;
    for (; i < n4; i += stride) p[i] = make_float4(0.f, 0.f, 0.f, 0.f);
}

// hstr = relu(s2 + gc2_b) (fp32) and half copy into cat[:, 512:1024]
__global__ void bias_relu_out(const float* __restrict__ in, const float* __restrict__ b,
                              float* __restrict__ outF, __half* __restrict__ outH,
                              long total4, int d4)
{
    long i = blockIdx.x * (long)blockDim.x + threadIdx.x;
    long stride = (long)gridDim.x * blockDim.x;
    for (; i < total4; i += stride) {
        int  c4  = (int)(i % d4);
        long row = i / d4;
        float4 x  = ((const float4*)in)[i];
        float4 bb = ((const float4*)b)[c4];
        float4 y;
        y.x = fmaxf(x.x + bb.x, 0.f);
        y.y = fmaxf(x.y + bb.y, 0.f);
        y.z = fmaxf(x.z + bb.z, 0.f);
        y.w = fmaxf(x.w + bb.w, 0.f);
        ((float4*)outF)[i] = y;
        __half2* hp = (__half2*)(outH + row * 1024 + 512 + c4 * 4);
        hp[0] = __floats2half2_rn(y.x, y.y);
        hp[1] = __floats2half2_rn(y.z, y.w);
    }
}

// ---------------------------------------------------------------------------
extern "C" void kernel_launch(void* const* d_in, const int* in_sizes, int n_in,
                              void* d_out, int out_size)
{
    const float* seq    = (const float*)d_in[0];
    const float* go     = (const float*)d_in[1];
    const int*   erow   = (const int*)  d_in[2];
    const int*   ecol   = (const int*)  d_in[3];
    const float* eval_  = (const float*)d_in[4];
    const float* mlp_w1 = (const float*)d_in[5];
    const float* mlp_b1 = (const float*)d_in[6];
    const float* mlp_w2 = (const float*)d_in[7];
    const float* mlp_b2 = (const float*)d_in[8];
    const float* gc1_w  = (const float*)d_in[9];
    const float* gc1_b  = (const float*)d_in[10];
    const float* gc2_w  = (const float*)d_in[11];
    const float* gc2_b  = (const float*)d_in[12];
    const float* se_w1  = (const float*)d_in[13];
    const float* se_b1  = (const float*)d_in[14];
    const float* se_w2  = (const float*)d_in[15];
    const float* se_b2  = (const float*)d_in[16];

    float* out  = (float*)d_out;
    float* hsem = out;
    float* hstr = out + (size_t)N_GO * NHID1;
    float* pred = out + (size_t)2 * N_GO * NHID1;

    __half *goh, *seqh, *t1h, *xh, *g2h, *uh, *soh, *cath, *sp1h, *wth;
    float *s1, *s2;
    cudaGetSymbolAddress((void**)&goh,  g_goh);
    cudaGetSymbolAddress((void**)&seqh, g_seqh);
    cudaGetSymbolAddress((void**)&t1h,  g_t1h);
    cudaGetSymbolAddress((void**)&xh,   g_xh);
    cudaGetSymbolAddress((void**)&g2h,  g_g2h);
    cudaGetSymbolAddress((void**)&uh,   g_uh);
    cudaGetSymbolAddress((void**)&soh,  g_soh);
    cudaGetSymbolAddress((void**)&cath, g_cath);
    cudaGetSymbolAddress((void**)&sp1h, g_sp1h);
    cudaGetSymbolAddress((void**)&s1,   g_s1);
    cudaGetSymbolAddress((void**)&s2,   g_s2);
    cudaGetSymbolAddress((void**)&wth,  g_wth);

    __half* wt_mlp1 = wth + 0;
    __half* wt_mlp2 = wth + 524288;
    __half* wt_gc1  = wth + 1048576;
    __half* wt_gc2  = wth + 1572864;
    __half* wt_se1  = wth + 2097152;
    __half* wt_se2  = wth + 3407872;

    cudaFuncSetAttribute(gemm_h, cudaFuncAttributeMaxDynamicSharedMemorySize,
                         GEMM_SMEM_BYTES);

    // one-time host objects (no device memory involved)
    static cudaStream_t sB = nullptr;
    static cudaEvent_t evFork = nullptr, evZ1 = nullptr, evW = nullptr,
                       evG2 = nullptr, evJoin = nullptr;
    if (sB == nullptr) {
        cudaStreamCreateWithFlags(&sB, cudaStreamNonBlocking);
        cudaEventCreateWithFlags(&evFork, cudaEventDisableTiming);
        cudaEventCreateWithFlags(&evZ1,   cudaEventDisableTiming);
        cudaEventCreateWithFlags(&evW,    cudaEventDisableTiming);
        cudaEventCreateWithFlags(&evG2,   cudaEventDisableTiming);
        cudaEventCreateWithFlags(&evJoin, cudaEventDisableTiming);
    }

    const int T = 256;
    dim3 tb(32, 8);
    const int MT_GO  = cdiv(N_GO, 128);   // 313
    const int MT_SEQ = SEQ_B / 128;       // 32
    const int SPMM_BLOCKS = 2048;

    // ---- origin stream: convert goh; fork immediately ----
    conv_h<<<2048, T>>>(go, goh, (long)N_GO * GO_FEAT / 4);
    cudaEventRecord(evFork, 0);
    cudaStreamWaitEvent(sB, evFork, 0);   // sB's FIRST op: join the capture

    // ---- stream B: zeros (parallel with conv_goh's tail) + weight prep ----
    zero_kernel<<<2048, T, 0, sB>>>((float4*)s1, (long)N_GO * NHID1 / 4);
    cudaEventRecord(evZ1, sB);
    zero_kernel<<<2048, T, 0, sB>>>((float4*)s2, (long)N_GO * NHID1 / 4);
    transpose_h<<<dim3(1024 / 32, 512 / 32),  tb, 0, sB>>>(gc1_w, wt_gc1, 512, 1024);
    transpose_h<<<dim3(512 / 32,  1024 / 32), tb, 0, sB>>>(gc2_w, wt_gc2, 1024, 512);
    cudaEventRecord(evW, sB);
    transpose_h<<<dim3(1024 / 32, 512 / 32),  tb, 0, sB>>>(mlp_w1, wt_mlp1, 512, 1024);
    transpose_h<<<dim3(512 / 32,  1024 / 32), tb, 0, sB>>>(mlp_w2, wt_mlp2, 1024, 512);
    transpose_h<<<dim3(1024 / 32, 1280 / 32), tb, 0, sB>>>(se_w1,  wt_se1,  1280, 1024);
    transpose_h<<<dim3(1024 / 32, 1024 / 32), tb, 0, sB>>>(se_w2,  wt_se2,  1024, 1024);
    conv_h<<<512, T, 0, sB>>>(seq, seqh, (long)SEQ_B * SEQ_FEAT / 4);
    // greedy: mlp branch (cath[:, :512] producer -- keep early)
    gemm_h<<<dim3(NHID0 / 128, MT_GO), GEMM_T, GEMM_SMEM_BYTES, sB>>>(
        goh, GO_FEAT, wt_mlp1, GO_FEAT, mlp_b1, t1h, 1, nullptr, 0,
        N_GO, NHID0, GO_FEAT, 1, 0);
    gemm_h<<<dim3(NHID1 / 128, MT_GO), GEMM_T, GEMM_SMEM_BYTES, sB>>>(
        t1h, NHID0, wt_mlp2, NHID0, mlp_b2, hsem, 0, cath, 1024,
        N_GO, NHID1, NHID0, 0, 0);

    // ---- origin stream: structure chain ----
    cudaStreamWaitEvent(0, evZ1, 0);
    spmm_h<<<SPMM_BLOCKS, T>>>(erow, ecol, eval_, goh, s1, N_EDGES, GO_FEAT);
    conv_h<<<2048, T>>>(s1, sp1h, (long)N_GO * NHID1 / 4);
    cudaStreamWaitEvent(0, evW, 0);
    gemm_h<<<dim3(NHID0 / 128, MT_GO), GEMM_T, GEMM_SMEM_BYTES>>>(
        sp1h, NHID1, wt_gc1, NHID1, gc1_b, xh, 1, nullptr, 0,
        N_GO, NHID0, GO_FEAT, 1, 0);
    gemm_h<<<dim3(NHID1 / 128, MT_GO), GEMM_T, GEMM_SMEM_BYTES>>>(
        xh, NHID0, wt_gc2, NHID0, nullptr, g2h, 1, nullptr, 0,
        N_GO, NHID1, NHID0, 0, 0);
    cudaEventRecord(evG2, 0);
    spmm_h<<<SPMM_BLOCKS, T>>>(erow, ecol, eval_, g2h, s2, N_EDGES, NHID1);
    bias_relu_out<<<2048, T>>>(s2, gc2_b, hstr, cath,
                               (long)N_GO * NHID1 / 4, NHID1 / 4);

    // ---- stream B: se1/se2 gated into the spmm2 window (fits: ~95us < ~165us) ----
    cudaStreamWaitEvent(sB, evG2, 0);
    gemm_h<<<dim3(NHID0 / 128, MT_SEQ), GEMM_T, GEMM_SMEM_BYTES, sB>>>(
        seqh, SEQ_FEAT, wt_se1, SEQ_FEAT, se_b1, uh, 1, nullptr, 0,
        SEQ_B, NHID0, SEQ_FEAT, 1, 0);
    gemm_h<<<dim3(NHID0 / 128, MT_SEQ), GEMM_T, GEMM_SMEM_BYTES, sB>>>(
        uh, NHID0, wt_se2, NHID0, se_b2, soh, 1, nullptr, 0,
        SEQ_B, NHID0, NHID0, 0, 0);
    cudaEventRecord(evJoin, sB);

    // ---- join, then single full prediction GEMM ----
    cudaStreamWaitEvent(0, evJoin, 0);
    gemm_h<<<dim3(MT_SEQ, MT_GO), GEMM_T, GEMM_SMEM_BYTES>>>(
        soh, NHID0, cath, 1024, nullptr, pred, 0, nullptr, 0,
        SEQ_B, N_GO, NHID0, 2, 1);
}

// round 16
// speedup vs baseline: 1.0068x; 1.0068x over previous
#include <cuda_runtime.h>
#include <cuda_fp16.h>
#include <cstdint>
#include <math.h>

// ---------------------------------------------------------------------------
// GraphNeuralNetwork forward. GEMMs on mma.sync fp16 (m16n8k16, fp32 accum).
// R16: R14 topology + 5-stage cp.async pipeline (deeper latency buffer for
// the streamed pred B-operand) + spmm sized to exactly one resident wave.
// ---------------------------------------------------------------------------

#define N_GO    40000
#define GO_FEAT 512
#define SEQ_FEAT 1280
#define NHID0   1024
#define NHID1   512
#define N_EDGES 640000
#define SEQ_B   4096

// ---------------- scratch (no runtime allocation allowed) ------------------
__device__ __half g_goh [(size_t)N_GO * GO_FEAT];
__device__ __half g_seqh[(size_t)SEQ_B * SEQ_FEAT];
__device__ __half g_t1h [(size_t)N_GO * NHID0];
__device__ __half g_xh  [(size_t)N_GO * NHID0];
__device__ __half g_g2h [(size_t)N_GO * NHID1];
__device__ __half g_uh  [(size_t)SEQ_B * NHID0];
__device__ __half g_soh [(size_t)SEQ_B * NHID0];
__device__ __half g_cath[(size_t)N_GO * 1024];
__device__ __half g_sp1h[(size_t)N_GO * NHID1];
__device__ float  g_s1  [(size_t)N_GO * NHID1];
__device__ float  g_s2  [(size_t)N_GO * NHID1];
__device__ __half g_wth[4456448];  // transposed half weights arena

static inline int cdiv(int a, int b) { return (a + b - 1) / b; }

// ---------------------------------------------------------------------------
__device__ __forceinline__ uint32_t smem_u32(const void* p) {
    uint32_t a;
    asm("{ .reg .u64 t; cvta.to.shared.u64 t, %1; cvt.u32.u64 %0, t; }"
        : "=r"(a) : "l"(p));
    return a;
}

__device__ __forceinline__ void mma_f16(float c[4], const uint32_t a[4],
                                        const uint32_t b[2]) {
    asm volatile(
        "mma.sync.aligned.m16n8k16.row.col.f32.f16.f16.f32 "
        "{%0,%1,%2,%3}, {%4,%5,%6,%7}, {%8,%9}, {%0,%1,%2,%3};"
        : "+f"(c[0]), "+f"(c[1]), "+f"(c[2]), "+f"(c[3])
        : "r"(a[0]), "r"(a[1]), "r"(a[2]), "r"(a[3]), "r"(b[0]), "r"(b[1]));
}

__device__ __forceinline__ void cp_async16(uint32_t dst, const void* src, bool valid) {
    int sz = valid ? 16 : 0;
    asm volatile("cp.async.cg.shared.global [%0], [%1], 16, %2;"
                 :: "r"(dst), "l"(src), "r"(sz) : "memory");
}
#define CP_COMMIT() asm volatile("cp.async.commit_group;" ::: "memory")
#define CP_WAIT3()  asm volatile("cp.async.wait_group 3;" ::: "memory")

// ---------------------------------------------------------------------------
// fp16 GEMM: C[M,N] = act(A[M,K] @ B[N,K]^T + bias). A rows lda halfs, B rows
// ldb halfs. CTA 128x128, K-tile 32, 4 warps (2x2, warp tile 64x64), 5-stage
// cp.async, pitch 40 halfs. act: 0=none 1=relu 2=sigmoid.
// C half if cHalf else float. Optional C2 (half, stride ldc2).
// swapxy: blockIdx.x indexes M.
// ---------------------------------------------------------------------------
#define PW 20
#define TILE_B 10240
#define STAGE_B (2 * TILE_B)
#define NSTAGE 5
#define GEMM_SMEM_BYTES (NSTAGE * STAGE_B)   // 102400
#define GEMM_T 128

__global__ void __launch_bounds__(GEMM_T, 2) gemm_h(
    const __half* __restrict__ A, int lda,
    const __half* __restrict__ B, int ldb,
    const float* __restrict__ bias,
    void* __restrict__ Cv, int cHalf,
    __half* __restrict__ C2, int ldc2,
    int M, int N, int K, int act, int swapxy)
{
    extern __shared__ __align__(16) char smc[];
    const uint32_t smem_base = smem_u32(smc);

    const int tid  = threadIdx.x;
    const int wid  = tid >> 5;
    const int lane = tid & 31;
    const int g    = lane >> 2;
    const int tig  = lane & 3;
    const int wm   = wid >> 1;
    const int wn   = wid & 1;
    const int m0   = (swapxy ? blockIdx.x : blockIdx.y) * 128;
    const int n0   = (swapxy ? blockIdx.y : blockIdx.x) * 128;

    const int nkt = K >> 5;

    auto issue = [&](int kt) {
        if (kt < nkt) {
            const int k0 = kt << 5;
            const uint32_t sbase = smem_base + (uint32_t)(kt % NSTAGE) * STAGE_B;
#pragma unroll
            for (int it = 0; it < 4; it++) {
                int idx = tid + it * GEMM_T;
                int r   = idx >> 2;
                int c   = idx & 3;
                uint32_t da = sbase + (uint32_t)(r * 80 + c * 16);
                cp_async16(da, A + (size_t)(m0 + r) * lda + k0 + c * 8, (m0 + r) < M);
                cp_async16(da + TILE_B, B + (size_t)(n0 + r) * ldb + k0 + c * 8,
                           (n0 + r) < N);
            }
        }
        CP_COMMIT();
    };

    float acc[4][8][4];
#pragma unroll
    for (int i = 0; i < 4; i++)
#pragma unroll
        for (int j = 0; j < 8; j++)
#pragma unroll
            for (int t = 0; t < 4; t++) acc[i][j][t] = 0.f;

    issue(0); issue(1); issue(2); issue(3);

    const int arow = (wm * 64 + g) * PW;
    const int brow = (wn * 64 + g) * PW;

    for (int kt = 0; kt < nkt; kt++) {
        CP_WAIT3();
        __syncthreads();
        issue(kt + 4);

        const uint32_t* as = (const uint32_t*)(smc + (kt % NSTAGE) * STAGE_B);
        const uint32_t* bs = as + TILE_B / 4;
#pragma unroll
        for (int kk = 0; kk < 2; kk++) {
            const int ko = kk * 8 + tig;
            uint32_t af[4][4];
#pragma unroll
            for (int i = 0; i < 4; i++) {
                int base = arow + i * 16 * PW;
                af[i][0] = as[base + ko];
                af[i][1] = as[base + 8 * PW + ko];
                af[i][2] = as[base + ko + 4];
                af[i][3] = as[base + 8 * PW + ko + 4];
            }
            uint32_t bf[8][2];
#pragma unroll
            for (int j = 0; j < 8; j++) {
                int base = brow + j * 8 * PW;
                bf[j][0] = bs[base + ko];
                bf[j][1] = bs[base + ko + 4];
            }
#pragma unroll
            for (int i = 0; i < 4; i++)
#pragma unroll
                for (int j = 0; j < 8; j++)
                    mma_f16(acc[i][j], af[i], bf[j]);
        }
    }

    // ---- epilogue ----
#pragma unroll
    for (int i = 0; i < 4; i++) {
        const int r0 = m0 + wm * 64 + 16 * i + g;
#pragma unroll
        for (int j = 0; j < 8; j++) {
            const int cn = n0 + wn * 64 + 8 * j + 2 * tig;
            if (cn >= N) continue;
            float b0 = 0.f, b1 = 0.f;
            if (bias != nullptr) { b0 = bias[cn]; b1 = bias[cn + 1]; }
#pragma unroll
            for (int h = 0; h < 2; h++) {
                const int r = r0 + h * 8;
                if (r >= M) continue;
                float x0 = acc[i][j][2 * h]     + b0;
                float x1 = acc[i][j][2 * h + 1] + b1;
                if (act == 1) { x0 = fmaxf(x0, 0.f); x1 = fmaxf(x1, 0.f); }
                else if (act == 2) {
                    x0 = __fdividef(1.f, 1.f + __expf(-x0));
                    x1 = __fdividef(1.f, 1.f + __expf(-x1));
                }
                if (cHalf)
                    *(__half2*)((__half*)Cv + (size_t)r * N + cn) =
                        __floats2half2_rn(x0, x1);
                else
                    *(float2*)((float*)Cv + (size_t)r * N + cn) =
                        make_float2(x0, x1);
                if (C2)
                    *(__half2*)(C2 + (size_t)r * ldc2 + cn) =
                        __floats2half2_rn(x0, x1);
            }
        }
    }
}

// ---------------------------------------------------------------------------
__global__ void transpose_h(const float* __restrict__ in, __half* __restrict__ out,
                            int R, int C)
{
    __shared__ float t[32][33];
    int bx = blockIdx.x * 32, by = blockIdx.y * 32;
    int x = bx + threadIdx.x;
    int y = by + threadIdx.y;
#pragma unroll
    for (int j = 0; j < 32; j += 8)
        if (y + j < R && x < C) t[threadIdx.y + j][threadIdx.x] = in[(size_t)(y + j) * C + x];
    __syncthreads();
    x = by + threadIdx.x;
    y = bx + threadIdx.y;
#pragma unroll
    for (int j = 0; j < 32; j += 8)
        if (y + j < C && x < R)
            out[(size_t)(y + j) * R + x] = __float2half_rn(t[threadIdx.x][threadIdx.y + j]);
}

__global__ void conv_h(const float* __restrict__ in, __half* __restrict__ out, long n4)
{
    long i = blockIdx.x * (long)blockDim.x + threadIdx.x;
    long stride = (long)gridDim.x * blockDim.x;
    for (; i < n4; i += stride) {
        float4 v = ((const float4*)in)[i];
        ((__half2*)out)[2 * i]     = __floats2half2_rn(v.x, v.y);
        ((__half2*)out)[2 * i + 1] = __floats2half2_rn(v.z, v.w);
    }
}

// ---------------------------------------------------------------------------
// SpMM (COO): out[row] += val * x[col], x fp16, fp32 float4 atomics.
// Persistent warps; two edges per iteration; grid = one resident wave.
// ---------------------------------------------------------------------------
__global__ void __launch_bounds__(256) spmm_h(
    const int* __restrict__ erow, const int* __restrict__ ecol,
    const float* __restrict__ eval, const __half* __restrict__ x,
    float* __restrict__ out, int nEdges, int d)
{
    const int lane = threadIdx.x & 31;
    const int gw   = (blockIdx.x * blockDim.x + threadIdx.x) >> 5;
    const int nw   = (gridDim.x * blockDim.x) >> 5;
    const int nch  = d >> 7;

    int e = gw * 2;
    const int step = nw * 2;
    for (; e + 1 < nEdges; e += step) {
        const int   r0 = erow[e],     r1 = erow[e + 1];
        const int   c0 = ecol[e],     c1 = ecol[e + 1];
        const float v0 = eval[e],     v1 = eval[e + 1];
        const __half2* xp0 = (const __half2*)(x + (size_t)c0 * d) + lane * 2;
        const __half2* xp1 = (const __half2*)(x + (size_t)c1 * d) + lane * 2;
        float4* op0 = (float4*)(out + (size_t)r0 * d) + lane;
        float4* op1 = (float4*)(out + (size_t)r1 * d) + lane;
        for (int ch = 0; ch < nch; ch++) {
            __half2 a0 = xp0[ch * 64], a1 = xp0[ch * 64 + 1];
            __half2 b0 = xp1[ch * 64], b1 = xp1[ch * 64 + 1];
            float2 fa0 = __half22float2(a0), fa1 = __half22float2(a1);
            float2 fb0 = __half22float2(b0), fb1 = __half22float2(b1);
            atomicAdd(op0 + ch * 32,
                      make_float4(v0 * fa0.x, v0 * fa0.y, v0 * fa1.x, v0 * fa1.y));
            atomicAdd(op1 + ch * 32,
                      make_float4(v1 * fb0.x, v1 * fb0.y, v1 * fb1.x, v1 * fb1.y));
        }
    }
    if (e < nEdges) {
        const int   r = erow[e];
        const int   c = ecol[e];
        const float v = eval[e];
        const __half2* xp = (const __half2*)(x + (size_t)c * d) + lane * 2;
        float4*        op = (float4*)(out + (size_t)r * d) + lane;
        for (int ch = 0; ch < nch; ch++) {
            float2 f0 = __half22float2(xp[ch * 64]);
            float2 f1 = __half22float2(xp[ch * 64 + 1]);
            atomicAdd(op + ch * 32,
                      make_float4(v * f0.x, v * f0.y, v * f1.x, v * f1.y));
        }
    }
}

__global__ void zero_kernel(float4* __restrict__ p, long n4)
{
    long i = blockIdx.x * (long)blockDim.x + threadIdx.x;
    long stride = (long)gridDim.x * blockDim.x;
    for (; i < n4; i += stride) p[i] = make_float4(0.f, 0.f, 0.f, 0.f);
}

// hstr = relu(s2 + gc2_b) (fp32) and half copy into cat[:, 512:1024]
__global__ void bias_relu_out(const float* __restrict__ in, const float* __restrict__ b,
                              float* __restrict__ outF, __half* __restrict__ outH,
                              long total4, int d4)
{
    long i = blockIdx.x * (long)blockDim.x + threadIdx.x;
    long stride = (long)gridDim.x * blockDim.x;
    for (; i < total4; i += stride) {
        int  c4  = (int)(i % d4);
        long row = i / d4;
        float4 x  = ((const float4*)in)[i];
        float4 bb = ((const float4*)b)[c4];
        float4 y;
        y.x = fmaxf(x.x + bb.x, 0.f);
        y.y = fmaxf(x.y + bb.y, 0.f);
        y.z = fmaxf(x.z + bb.z, 0.f);
        y.w = fmaxf(x.w + bb.w, 0.f);
        ((float4*)outF)[i] = y;
        __half2* hp = (__half2*)(outH + row * 1024 + 512 + c4 * 4);
        hp[0] = __floats2half2_rn(y.x, y.y);
        hp[1] = __floats2half2_rn(y.z, y.w);
    }
}

// ---------------------------------------------------------------------------
extern "C" void kernel_launch(void* const* d_in, const int* in_sizes, int n_in,
                              void* d_out, int out_size)
{
    const float* seq    = (const float*)d_in[0];
    const float* go     = (const float*)d_in[1];
    const int*   erow   = (const int*)  d_in[2];
    const int*   ecol   = (const int*)  d_in[3];
    const float* eval_  = (const float*)d_in[4];
    const float* mlp_w1 = (const float*)d_in[5];
    const float* mlp_b1 = (const float*)d_in[6];
    const float* mlp_w2 = (const float*)d_in[7];
    const float* mlp_b2 = (const float*)d_in[8];
    const float* gc1_w  = (const float*)d_in[9];
    const float* gc1_b  = (const float*)d_in[10];
    const float* gc2_w  = (const float*)d_in[11];
    const float* gc2_b  = (const float*)d_in[12];
    const float* se_w1  = (const float*)d_in[13];
    const float* se_b1  = (const float*)d_in[14];
    const float* se_w2  = (const float*)d_in[15];
    const float* se_b2  = (const float*)d_in[16];

    float* out  = (float*)d_out;
    float* hsem = out;
    float* hstr = out + (size_t)N_GO * NHID1;
    float* pred = out + (size_t)2 * N_GO * NHID1;

    __half *goh, *seqh, *t1h, *xh, *g2h, *uh, *soh, *cath, *sp1h, *wth;
    float *s1, *s2;
    cudaGetSymbolAddress((void**)&goh,  g_goh);
    cudaGetSymbolAddress((void**)&seqh, g_seqh);
    cudaGetSymbolAddress((void**)&t1h,  g_t1h);
    cudaGetSymbolAddress((void**)&xh,   g_xh);
    cudaGetSymbolAddress((void**)&g2h,  g_g2h);
    cudaGetSymbolAddress((void**)&uh,   g_uh);
    cudaGetSymbolAddress((void**)&soh,  g_soh);
    cudaGetSymbolAddress((void**)&cath, g_cath);
    cudaGetSymbolAddress((void**)&sp1h, g_sp1h);
    cudaGetSymbolAddress((void**)&s1,   g_s1);
    cudaGetSymbolAddress((void**)&s2,   g_s2);
    cudaGetSymbolAddress((void**)&wth,  g_wth);

    __half* wt_mlp1 = wth + 0;
    __half* wt_mlp2 = wth + 524288;
    __half* wt_gc1  = wth + 1048576;
    __half* wt_gc2  = wth + 1572864;
    __half* wt_se1  = wth + 2097152;
    __half* wt_se2  = wth + 3407872;

    cudaFuncSetAttribute(gemm_h, cudaFuncAttributeMaxDynamicSharedMemorySize,
                         GEMM_SMEM_BYTES);

    // one-time host objects (no device memory involved)
    static cudaStream_t sB = nullptr;
    static cudaEvent_t evFork = nullptr, evW = nullptr, evJoin = nullptr;
    if (sB == nullptr) {
        cudaStreamCreateWithFlags(&sB, cudaStreamNonBlocking);
        cudaEventCreateWithFlags(&evFork, cudaEventDisableTiming);
        cudaEventCreateWithFlags(&evW,    cudaEventDisableTiming);
        cudaEventCreateWithFlags(&evJoin, cudaEventDisableTiming);
    }

    const int T = 256;
    dim3 tb(32, 8);
    const int MT_GO  = cdiv(N_GO, 128);   // 313
    const int MT_SEQ = SEQ_B / 128;       // 32
    const int SPMM_BLOCKS = 1184;         // 148 SMs x 8 resident blocks

    // ---- origin stream: convert goh, then FORK (legal capture join) ----
    conv_h<<<2048, T>>>(go, goh, (long)N_GO * GO_FEAT / 4);
    cudaEventRecord(evFork, 0);
    cudaStreamWaitEvent(sB, evFork, 0);   // sB's FIRST op: join the capture

    // ---- origin stream: structure chain start (spmm-heavy) ----
    zero_kernel<<<2048, T>>>((float4*)s1, (long)N_GO * NHID1 / 4);
    spmm_h<<<SPMM_BLOCKS, T>>>(erow, ecol, eval_, goh, s1, N_EDGES, GO_FEAT);
    conv_h<<<2048, T>>>(s1, sp1h, (long)N_GO * NHID1 / 4);

    // ---- stream B: s2 zero + weight prep, then semantic + sequence GEMMs ----
    zero_kernel<<<2048, T, 0, sB>>>((float4*)s2, (long)N_GO * NHID1 / 4);
    transpose_h<<<dim3(1024 / 32, 512 / 32),  tb, 0, sB>>>(gc1_w, wt_gc1, 512, 1024);
    transpose_h<<<dim3(512 / 32,  1024 / 32), tb, 0, sB>>>(gc2_w, wt_gc2, 1024, 512);
    cudaEventRecord(evW, sB);
    transpose_h<<<dim3(1024 / 32, 512 / 32),  tb, 0, sB>>>(mlp_w1, wt_mlp1, 512, 1024);
    transpose_h<<<dim3(512 / 32,  1024 / 32), tb, 0, sB>>>(mlp_w2, wt_mlp2, 1024, 512);
    transpose_h<<<dim3(1024 / 32, 1280 / 32), tb, 0, sB>>>(se_w1,  wt_se1,  1280, 1024);
    transpose_h<<<dim3(1024 / 32, 1024 / 32), tb, 0, sB>>>(se_w2,  wt_se2,  1024, 1024);
    conv_h<<<512, T, 0, sB>>>(seq, seqh, (long)SEQ_B * SEQ_FEAT / 4);
    gemm_h<<<dim3(NHID0 / 128, MT_GO), GEMM_T, GEMM_SMEM_BYTES, sB>>>(
        goh, GO_FEAT, wt_mlp1, GO_FEAT, mlp_b1, t1h, 1, nullptr, 0,
        N_GO, NHID0, GO_FEAT, 1, 0);
    gemm_h<<<dim3(NHID1 / 128, MT_GO), GEMM_T, GEMM_SMEM_BYTES, sB>>>(
        t1h, NHID0, wt_mlp2, NHID0, mlp_b2, hsem, 0, cath, 1024,
        N_GO, NHID1, NHID0, 0, 0);
    gemm_h<<<dim3(NHID0 / 128, MT_SEQ), GEMM_T, GEMM_SMEM_BYTES, sB>>>(
        seqh, SEQ_FEAT, wt_se1, SEQ_FEAT, se_b1, uh, 1, nullptr, 0,
        SEQ_B, NHID0, SEQ_FEAT, 1, 0);
    gemm_h<<<dim3(NHID0 / 128, MT_SEQ), GEMM_T, GEMM_SMEM_BYTES, sB>>>(
        uh, NHID0, wt_se2, NHID0, se_b2, soh, 1, nullptr, 0,
        SEQ_B, NHID0, NHID0, 0, 0);
    cudaEventRecord(evJoin, sB);

    // ---- origin stream: rest of structure chain ----
    cudaStreamWaitEvent(0, evW, 0);
    gemm_h<<<dim3(NHID0 / 128, MT_GO), GEMM_T, GEMM_SMEM_BYTES>>>(
        sp1h, NHID1, wt_gc1, NHID1, gc1_b, xh, 1, nullptr, 0,
        N_GO, NHID0, GO_FEAT, 1, 0);
    gemm_h<<<dim3(NHID1 / 128, MT_GO), GEMM_T, GEMM_SMEM_BYTES>>>(
        xh, NHID0, wt_gc2, NHID0, nullptr, g2h, 1, nullptr, 0,
        N_GO, NHID1, NHID0, 0, 0);
    spmm_h<<<SPMM_BLOCKS, T>>>(erow, ecol, eval_, g2h, s2, N_EDGES, NHID1);
    bias_relu_out<<<2048, T>>>(s2, gc2_b, hstr, cath,
                               (long)N_GO * NHID1 / 4, NHID1 / 4);

    // ---- join, then single full prediction GEMM ----
    cudaStreamWaitEvent(0, evJoin, 0);
    gemm_h<<<dim3(MT_SEQ, MT_GO), GEMM_T, GEMM_SMEM_BYTES>>>(
        soh, NHID0, cath, 1024, nullptr, pred, 0, nullptr, 0,
        SEQ_B, N_GO, NHID0, 2, 1);
}

// round 17
// speedup vs baseline: 1.0139x; 1.0071x over previous
#include <cuda_runtime.h>
#include <cuda_fp16.h>
#include <cstdint>
#include <math.h>

// ---------------------------------------------------------------------------
// GraphNeuralNetwork forward. GEMMs on mma.sync fp16 (m16n8k16, fp32 accum).
// R17: R16 + zero_s1 moved to stream B (shrinks serial spmm1 prefix) +
// one-wave grid for conv_sp1. All other components byte-identical to R16.
// ---------------------------------------------------------------------------

#define N_GO    40000
#define GO_FEAT 512
#define SEQ_FEAT 1280
#define NHID0   1024
#define NHID1   512
#define N_EDGES 640000
#define SEQ_B   4096

// ---------------- scratch (no runtime allocation allowed) ------------------
__device__ __half g_goh [(size_t)N_GO * GO_FEAT];
__device__ __half g_seqh[(size_t)SEQ_B * SEQ_FEAT];
__device__ __half g_t1h [(size_t)N_GO * NHID0];
__device__ __half g_xh  [(size_t)N_GO * NHID0];
__device__ __half g_g2h [(size_t)N_GO * NHID1];
__device__ __half g_uh  [(size_t)SEQ_B * NHID0];
__device__ __half g_soh [(size_t)SEQ_B * NHID0];
__device__ __half g_cath[(size_t)N_GO * 1024];
__device__ __half g_sp1h[(size_t)N_GO * NHID1];
__device__ float  g_s1  [(size_t)N_GO * NHID1];
__device__ float  g_s2  [(size_t)N_GO * NHID1];
__device__ __half g_wth[4456448];  // transposed half weights arena

static inline int cdiv(int a, int b) { return (a + b - 1) / b; }

// ---------------------------------------------------------------------------
__device__ __forceinline__ uint32_t smem_u32(const void* p) {
    uint32_t a;
    asm("{ .reg .u64 t; cvta.to.shared.u64 t, %1; cvt.u32.u64 %0, t; }"
        : "=r"(a) : "l"(p));
    return a;
}

__device__ __forceinline__ void mma_f16(float c[4], const uint32_t a[4],
                                        const uint32_t b[2]) {
    asm volatile(
        "mma.sync.aligned.m16n8k16.row.col.f32.f16.f16.f32 "
        "{%0,%1,%2,%3}, {%4,%5,%6,%7}, {%8,%9}, {%0,%1,%2,%3};"
        : "+f"(c[0]), "+f"(c[1]), "+f"(c[2]), "+f"(c[3])
        : "r"(a[0]), "r"(a[1]), "r"(a[2]), "r"(a[3]), "r"(b[0]), "r"(b[1]));
}

__device__ __forceinline__ void cp_async16(uint32_t dst, const void* src, bool valid) {
    int sz = valid ? 16 : 0;
    asm volatile("cp.async.cg.shared.global [%0], [%1], 16, %2;"
                 :: "r"(dst), "l"(src), "r"(sz) : "memory");
}
#define CP_COMMIT() asm volatile("cp.async.commit_group;" ::: "memory")
#define CP_WAIT3()  asm volatile("cp.async.wait_group 3;" ::: "memory")

// ---------------------------------------------------------------------------
// fp16 GEMM: C[M,N] = act(A[M,K] @ B[N,K]^T + bias). A rows lda halfs, B rows
// ldb halfs. CTA 128x128, K-tile 32, 4 warps (2x2, warp tile 64x64), 5-stage
// cp.async, pitch 40 halfs. act: 0=none 1=relu 2=sigmoid.
// C half if cHalf else float. Optional C2 (half, stride ldc2).
// swapxy: blockIdx.x indexes M.
// ---------------------------------------------------------------------------
#define PW 20
#define TILE_B 10240
#define STAGE_B (2 * TILE_B)
#define NSTAGE 5
#define GEMM_SMEM_BYTES (NSTAGE * STAGE_B)   // 102400
#define GEMM_T 128

__global__ void __launch_bounds__(GEMM_T, 2) gemm_h(
    const __half* __restrict__ A, int lda,
    const __half* __restrict__ B, int ldb,
    const float* __restrict__ bias,
    void* __restrict__ Cv, int cHalf,
    __half* __restrict__ C2, int ldc2,
    int M, int N, int K, int act, int swapxy)
{
    extern __shared__ __align__(16) char smc[];
    const uint32_t smem_base = smem_u32(smc);

    const int tid  = threadIdx.x;
    const int wid  = tid >> 5;
    const int lane = tid & 31;
    const int g    = lane >> 2;
    const int tig  = lane & 3;
    const int wm   = wid >> 1;
    const int wn   = wid & 1;
    const int m0   = (swapxy ? blockIdx.x : blockIdx.y) * 128;
    const int n0   = (swapxy ? blockIdx.y : blockIdx.x) * 128;

    const int nkt = K >> 5;

    auto issue = [&](int kt) {
        if (kt < nkt) {
            const int k0 = kt << 5;
            const uint32_t sbase = smem_base + (uint32_t)(kt % NSTAGE) * STAGE_B;
#pragma unroll
            for (int it = 0; it < 4; it++) {
                int idx = tid + it * GEMM_T;
                int r   = idx >> 2;
                int c   = idx & 3;
                uint32_t da = sbase + (uint32_t)(r * 80 + c * 16);
                cp_async16(da, A + (size_t)(m0 + r) * lda + k0 + c * 8, (m0 + r) < M);
                cp_async16(da + TILE_B, B + (size_t)(n0 + r) * ldb + k0 + c * 8,
                           (n0 + r) < N);
            }
        }
        CP_COMMIT();
    };

    float acc[4][8][4];
#pragma unroll
    for (int i = 0; i < 4; i++)
#pragma unroll
        for (int j = 0; j < 8; j++)
#pragma unroll
            for (int t = 0; t < 4; t++) acc[i][j][t] = 0.f;

    issue(0); issue(1); issue(2); issue(3);

    const int arow = (wm * 64 + g) * PW;
    const int brow = (wn * 64 + g) * PW;

    for (int kt = 0; kt < nkt; kt++) {
        CP_WAIT3();
        __syncthreads();
        issue(kt + 4);

        const uint32_t* as = (const uint32_t*)(smc + (kt % NSTAGE) * STAGE_B);
        const uint32_t* bs = as + TILE_B / 4;
#pragma unroll
        for (int kk = 0; kk < 2; kk++) {
            const int ko = kk * 8 + tig;
            uint32_t af[4][4];
#pragma unroll
            for (int i = 0; i < 4; i++) {
                int base = arow + i * 16 * PW;
                af[i][0] = as[base + ko];
                af[i][1] = as[base + 8 * PW + ko];
                af[i][2] = as[base + ko + 4];
                af[i][3] = as[base + 8 * PW + ko + 4];
            }
            uint32_t bf[8][2];
#pragma unroll
            for (int j = 0; j < 8; j++) {
                int base = brow + j * 8 * PW;
                bf[j][0] = bs[base + ko];
                bf[j][1] = bs[base + ko + 4];
            }
#pragma unroll
            for (int i = 0; i < 4; i++)
#pragma unroll
                for (int j = 0; j < 8; j++)
                    mma_f16(acc[i][j], af[i], bf[j]);
        }
    }

    // ---- epilogue ----
#pragma unroll
    for (int i = 0; i < 4; i++) {
        const int r0 = m0 + wm * 64 + 16 * i + g;
#pragma unroll
        for (int j = 0; j < 8; j++) {
            const int cn = n0 + wn * 64 + 8 * j + 2 * tig;
            if (cn >= N) continue;
            float b0 = 0.f, b1 = 0.f;
            if (bias != nullptr) { b0 = bias[cn]; b1 = bias[cn + 1]; }
#pragma unroll
            for (int h = 0; h < 2; h++) {
                const int r = r0 + h * 8;
                if (r >= M) continue;
                float x0 = acc[i][j][2 * h]     + b0;
                float x1 = acc[i][j][2 * h + 1] + b1;
                if (act == 1) { x0 = fmaxf(x0, 0.f); x1 = fmaxf(x1, 0.f); }
                else if (act == 2) {
                    x0 = __fdividef(1.f, 1.f + __expf(-x0));
                    x1 = __fdividef(1.f, 1.f + __expf(-x1));
                }
                if (cHalf)
                    *(__half2*)((__half*)Cv + (size_t)r * N + cn) =
                        __floats2half2_rn(x0, x1);
                else
                    *(float2*)((float*)Cv + (size_t)r * N + cn) =
                        make_float2(x0, x1);
                if (C2)
                    *(__half2*)(C2 + (size_t)r * ldc2 + cn) =
                        __floats2half2_rn(x0, x1);
            }
        }
    }
}

// ---------------------------------------------------------------------------
__global__ void transpose_h(const float* __restrict__ in, __half* __restrict__ out,
                            int R, int C)
{
    __shared__ float t[32][33];
    int bx = blockIdx.x * 32, by = blockIdx.y * 32;
    int x = bx + threadIdx.x;
    int y = by + threadIdx.y;
#pragma unroll
    for (int j = 0; j < 32; j += 8)
        if (y + j < R && x < C) t[threadIdx.y + j][threadIdx.x] = in[(size_t)(y + j) * C + x];
    __syncthreads();
    x = by + threadIdx.x;
    y = bx + threadIdx.y;
#pragma unroll
    for (int j = 0; j < 32; j += 8)
        if (y + j < C && x < R)
            out[(size_t)(y + j) * R + x] = __float2half_rn(t[threadIdx.x][threadIdx.y + j]);
}

__global__ void conv_h(const float* __restrict__ in, __half* __restrict__ out, long n4)
{
    long i = blockIdx.x * (long)blockDim.x + threadIdx.x;
    long stride = (long)gridDim.x * blockDim.x;
    for (; i < n4; i += stride) {
        float4 v = ((const float4*)in)[i];
        ((__half2*)out)[2 * i]     = __floats2half2_rn(v.x, v.y);
        ((__half2*)out)[2 * i + 1] = __floats2half2_rn(v.z, v.w);
    }
}

// ---------------------------------------------------------------------------
// SpMM (COO): out[row] += val * x[col], x fp16, fp32 float4 atomics.
// Persistent warps; two edges per iteration; grid = one resident wave.
// ---------------------------------------------------------------------------
__global__ void __launch_bounds__(256) spmm_h(
    const int* __restrict__ erow, const int* __restrict__ ecol,
    const float* __restrict__ eval, const __half* __restrict__ x,
    float* __restrict__ out, int nEdges, int d)
{
    const int lane = threadIdx.x & 31;
    const int gw   = (blockIdx.x * blockDim.x + threadIdx.x) >> 5;
    const int nw   = (gridDim.x * blockDim.x) >> 5;
    const int nch  = d >> 7;

    int e = gw * 2;
    const int step = nw * 2;
    for (; e + 1 < nEdges; e += step) {
        const int   r0 = erow[e],     r1 = erow[e + 1];
        const int   c0 = ecol[e],     c1 = ecol[e + 1];
        const float v0 = eval[e],     v1 = eval[e + 1];
        const __half2* xp0 = (const __half2*)(x + (size_t)c0 * d) + lane * 2;
        const __half2* xp1 = (const __half2*)(x + (size_t)c1 * d) + lane * 2;
        float4* op0 = (float4*)(out + (size_t)r0 * d) + lane;
        float4* op1 = (float4*)(out + (size_t)r1 * d) + lane;
        for (int ch = 0; ch < nch; ch++) {
            __half2 a0 = xp0[ch * 64], a1 = xp0[ch * 64 + 1];
            __half2 b0 = xp1[ch * 64], b1 = xp1[ch * 64 + 1];
            float2 fa0 = __half22float2(a0), fa1 = __half22float2(a1);
            float2 fb0 = __half22float2(b0), fb1 = __half22float2(b1);
            atomicAdd(op0 + ch * 32,
                      make_float4(v0 * fa0.x, v0 * fa0.y, v0 * fa1.x, v0 * fa1.y));
            atomicAdd(op1 + ch * 32,
                      make_float4(v1 * fb0.x, v1 * fb0.y, v1 * fb1.x, v1 * fb1.y));
        }
    }
    if (e < nEdges) {
        const int   r = erow[e];
        const int   c = ecol[e];
        const float v = eval[e];
        const __half2* xp = (const __half2*)(x + (size_t)c * d) + lane * 2;
        float4*        op = (float4*)(out + (size_t)r * d) + lane;
        for (int ch = 0; ch < nch; ch++) {
            float2 f0 = __half22float2(xp[ch * 64]);
            float2 f1 = __half22float2(xp[ch * 64 + 1]);
            atomicAdd(op + ch * 32,
                      make_float4(v * f0.x, v * f0.y, v * f1.x, v * f1.y));
        }
    }
}

__global__ void zero_kernel(float4* __restrict__ p, long n4)
{
    long i = blockIdx.x * (long)blockDim.x + threadIdx.x;
    long stride = (long)gridDim.x * blockDim.x;
    for (; i < n4; i += stride) p[i] = make_float4(0.f, 0.f, 0.f, 0.f);
}

// hstr = relu(s2 + gc2_b) (fp32) and half copy into cat[:, 512:1024]
__global__ void bias_relu_out(const float* __restrict__ in, const float* __restrict__ b,
                              float* __restrict__ outF, __half* __restrict__ outH,
                              long total4, int d4)
{
    long i = blockIdx.x * (long)blockDim.x + threadIdx.x;
    long stride = (long)gridDim.x * blockDim.x;
    for (; i < total4; i += stride) {
        int  c4  = (int)(i % d4);
        long row = i / d4;
        float4 x  = ((const float4*)in)[i];
        float4 bb = ((const float4*)b)[c4];
        float4 y;
        y.x = fmaxf(x.x + bb.x, 0.f);
        y.y = fmaxf(x.y + bb.y, 0.f);
        y.z = fmaxf(x.z + bb.z, 0.f);
        y.w = fmaxf(x.w + bb.w, 0.f);
        ((float4*)outF)[i] = y;
        __half2* hp = (__half2*)(outH + row * 1024 + 512 + c4 * 4);
        hp[0] = __floats2half2_rn(y.x, y.y);
        hp[1] = __floats2half2_rn(y.z, y.w);
    }
}

// ---------------------------------------------------------------------------
extern "C" void kernel_launch(void* const* d_in, const int* in_sizes, int n_in,
                              void* d_out, int out_size)
{
    const float* seq    = (const float*)d_in[0];
    const float* go     = (const float*)d_in[1];
    const int*   erow   = (const int*)  d_in[2];
    const int*   ecol   = (const int*)  d_in[3];
    const float* eval_  = (const float*)d_in[4];
    const float* mlp_w1 = (const float*)d_in[5];
    const float* mlp_b1 = (const float*)d_in[6];
    const float* mlp_w2 = (const float*)d_in[7];
    const float* mlp_b2 = (const float*)d_in[8];
    const float* gc1_w  = (const float*)d_in[9];
    const float* gc1_b  = (const float*)d_in[10];
    const float* gc2_w  = (const float*)d_in[11];
    const float* gc2_b  = (const float*)d_in[12];
    const float* se_w1  = (const float*)d_in[13];
    const float* se_b1  = (const float*)d_in[14];
    const float* se_w2  = (const float*)d_in[15];
    const float* se_b2  = (const float*)d_in[16];

    float* out  = (float*)d_out;
    float* hsem = out;
    float* hstr = out + (size_t)N_GO * NHID1;
    float* pred = out + (size_t)2 * N_GO * NHID1;

    __half *goh, *seqh, *t1h, *xh, *g2h, *uh, *soh, *cath, *sp1h, *wth;
    float *s1, *s2;
    cudaGetSymbolAddress((void**)&goh,  g_goh);
    cudaGetSymbolAddress((void**)&seqh, g_seqh);
    cudaGetSymbolAddress((void**)&t1h,  g_t1h);
    cudaGetSymbolAddress((void**)&xh,   g_xh);
    cudaGetSymbolAddress((void**)&g2h,  g_g2h);
    cudaGetSymbolAddress((void**)&uh,   g_uh);
    cudaGetSymbolAddress((void**)&soh,  g_soh);
    cudaGetSymbolAddress((void**)&cath, g_cath);
    cudaGetSymbolAddress((void**)&sp1h, g_sp1h);
    cudaGetSymbolAddress((void**)&s1,   g_s1);
    cudaGetSymbolAddress((void**)&s2,   g_s2);
    cudaGetSymbolAddress((void**)&wth,  g_wth);

    __half* wt_mlp1 = wth + 0;
    __half* wt_mlp2 = wth + 524288;
    __half* wt_gc1  = wth + 1048576;
    __half* wt_gc2  = wth + 1572864;
    __half* wt_se1  = wth + 2097152;
    __half* wt_se2  = wth + 3407872;

    cudaFuncSetAttribute(gemm_h, cudaFuncAttributeMaxDynamicSharedMemorySize,
                         GEMM_SMEM_BYTES);

    // one-time host objects (no device memory involved)
    static cudaStream_t sB = nullptr;
    static cudaEvent_t evFork = nullptr, evZ1 = nullptr, evW = nullptr,
                       evJoin = nullptr;
    if (sB == nullptr) {
        cudaStreamCreateWithFlags(&sB, cudaStreamNonBlocking);
        cudaEventCreateWithFlags(&evFork, cudaEventDisableTiming);
        cudaEventCreateWithFlags(&evZ1,   cudaEventDisableTiming);
        cudaEventCreateWithFlags(&evW,    cudaEventDisableTiming);
        cudaEventCreateWithFlags(&evJoin, cudaEventDisableTiming);
    }

    const int T = 256;
    dim3 tb(32, 8);
    const int MT_GO  = cdiv(N_GO, 128);   // 313
    const int MT_SEQ = SEQ_B / 128;       // 32
    const int SPMM_BLOCKS = 1184;         // 148 SMs x 8 resident blocks

    // ---- origin stream: convert goh; fork immediately after first launch ----
    conv_h<<<2048, T>>>(go, goh, (long)N_GO * GO_FEAT / 4);
    cudaEventRecord(evFork, 0);
    cudaStreamWaitEvent(sB, evFork, 0);   // sB's FIRST op: join the capture

    // ---- stream B: zero s1 (overlaps conv_goh tail) + s2 + weight prep ----
    zero_kernel<<<1184, T, 0, sB>>>((float4*)s1, (long)N_GO * NHID1 / 4);
    cudaEventRecord(evZ1, sB);
    zero_kernel<<<1184, T, 0, sB>>>((float4*)s2, (long)N_GO * NHID1 / 4);
    transpose_h<<<dim3(1024 / 32, 512 / 32),  tb, 0, sB>>>(gc1_w, wt_gc1, 512, 1024);
    transpose_h<<<dim3(512 / 32,  1024 / 32), tb, 0, sB>>>(gc2_w, wt_gc2, 1024, 512);
    cudaEventRecord(evW, sB);
    transpose_h<<<dim3(1024 / 32, 512 / 32),  tb, 0, sB>>>(mlp_w1, wt_mlp1, 512, 1024);
    transpose_h<<<dim3(512 / 32,  1024 / 32), tb, 0, sB>>>(mlp_w2, wt_mlp2, 1024, 512);
    transpose_h<<<dim3(1024 / 32, 1280 / 32), tb, 0, sB>>>(se_w1,  wt_se1,  1280, 1024);
    transpose_h<<<dim3(1024 / 32, 1024 / 32), tb, 0, sB>>>(se_w2,  wt_se2,  1024, 1024);
    conv_h<<<512, T, 0, sB>>>(seq, seqh, (long)SEQ_B * SEQ_FEAT / 4);
    gemm_h<<<dim3(NHID0 / 128, MT_GO), GEMM_T, GEMM_SMEM_BYTES, sB>>>(
        goh, GO_FEAT, wt_mlp1, GO_FEAT, mlp_b1, t1h, 1, nullptr, 0,
        N_GO, NHID0, GO_FEAT, 1, 0);
    gemm_h<<<dim3(NHID1 / 128, MT_GO), GEMM_T, GEMM_SMEM_BYTES, sB>>>(
        t1h, NHID0, wt_mlp2, NHID0, mlp_b2, hsem, 0, cath, 1024,
        N_GO, NHID1, NHID0, 0, 0);
    gemm_h<<<dim3(NHID0 / 128, MT_SEQ), GEMM_T, GEMM_SMEM_BYTES, sB>>>(
        seqh, SEQ_FEAT, wt_se1, SEQ_FEAT, se_b1, uh, 1, nullptr, 0,
        SEQ_B, NHID0, SEQ_FEAT, 1, 0);
    gemm_h<<<dim3(NHID0 / 128, MT_SEQ), GEMM_T, GEMM_SMEM_BYTES, sB>>>(
        uh, NHID0, wt_se2, NHID0, se_b2, soh, 1, nullptr, 0,
        SEQ_B, NHID0, NHID0, 0, 0);
    cudaEventRecord(evJoin, sB);

    // ---- origin stream: structure chain ----
    cudaStreamWaitEvent(0, evZ1, 0);
    spmm_h<<<SPMM_BLOCKS, T>>>(erow, ecol, eval_, goh, s1, N_EDGES, GO_FEAT);
    conv_h<<<1184, T>>>(s1, sp1h, (long)N_GO * NHID1 / 4);
    cudaStreamWaitEvent(0, evW, 0);
    gemm_h<<<dim3(NHID0 / 128, MT_GO), GEMM_T, GEMM_SMEM_BYTES>>>(
        sp1h, NHID1, wt_gc1, NHID1, gc1_b, xh, 1, nullptr, 0,
        N_GO, NHID0, GO_FEAT, 1, 0);
    gemm_h<<<dim3(NHID1 / 128, MT_GO), GEMM_T, GEMM_SMEM_BYTES>>>(
        xh, NHID0, wt_gc2, NHID0, nullptr, g2h, 1, nullptr, 0,
        N_GO, NHID1, NHID0, 0, 0);
    spmm_h<<<SPMM_BLOCKS, T>>>(erow, ecol, eval_, g2h, s2, N_EDGES, NHID1);
    bias_relu_out<<<1184, T>>>(s2, gc2_b, hstr, cath,
                               (long)N_GO * NHID1 / 4, NHID1 / 4);

    // ---- join, then single full prediction GEMM ----
    cudaStreamWaitEvent(0, evJoin, 0);
    gemm_h<<<dim3(MT_SEQ, MT_GO), GEMM_T, GEMM_SMEM_BYTES>>>(
        soh, NHID0, cath, 1024, nullptr, pred, 0, nullptr, 0,
        SEQ_B, N_GO, NHID0, 2, 1);
}